// round 2
// baseline (speedup 1.0000x reference)
#include <cuda_runtime.h>

#define SENS 61
#define HID  64
#define NSTEPS 10
#define TPB  128

// Dormand–Prince 5(4) tableau (double-evaluated, rounded to f32 to match JAX weak typing)
__constant__ float c_A[6][5] = {
  {0.f, 0.f, 0.f, 0.f, 0.f},
  {(float)(1.0/5.0), 0.f, 0.f, 0.f, 0.f},
  {(float)(3.0/40.0), (float)(9.0/40.0), 0.f, 0.f, 0.f},
  {(float)(44.0/45.0), (float)(-56.0/15.0), (float)(32.0/9.0), 0.f, 0.f},
  {(float)(19372.0/6561.0), (float)(-25360.0/2187.0), (float)(64448.0/6561.0), (float)(-212.0/729.0), 0.f},
  {(float)(9017.0/3168.0), (float)(-355.0/33.0), (float)(46732.0/5247.0), (float)(49.0/176.0), (float)(-5103.0/18656.0)}
};
__constant__ float c_C[6] = {0.f, 0.2f, 0.3f, 0.8f, (float)(8.0/9.0), 1.f};
__constant__ float c_B[6] = {(float)(35.0/384.0), 0.f, (float)(500.0/1113.0),
                             (float)(125.0/192.0), (float)(-2187.0/6784.0), (float)(11.0/84.0)};

__device__ __forceinline__ float ftanh(float x) {
  // tanh(x) = 1 - 2/(exp(2x)+1); __expf + fast divide: ~1e-6 rel err, MUFU-cheap
  float e = __expf(x + x);
  return 1.0f - __fdividef(2.0f, e + 1.0f);
}

// Shared layout (floats):
//   sW1y : [64][4]  rows {W1[0], W1[1], W1[2], W1[64]} transposed  (y + t weights)
//   sW2  : [64][64]
//   sW3  : [64][4]  (col 3 zero-padded)
//   sB2  : [64]
//   sB3  : [4]
//   sS1  : [64][TPB] per-thread sensory contribution incl. b1 (conflict-free: lane stride 4B)
#define OFF_W1Y 0
#define OFF_W2  (OFF_W1Y + HID*4)
#define OFF_W3  (OFF_W2 + HID*HID)
#define OFF_B2  (OFF_W3 + HID*4)
#define OFF_B3  (OFF_B2 + HID)
#define OFF_S1  (OFF_B3 + 4)
#define SMEM_FLOATS (OFF_S1 + HID*TPB)

__global__ void __launch_bounds__(TPB)
ode_kernel(const float* __restrict__ pad0, const float* __restrict__ sens,
           const float* __restrict__ W1, const float* __restrict__ b1,
           const float* __restrict__ W2, const float* __restrict__ b2,
           const float* __restrict__ W3, const float* __restrict__ b3,
           const float* __restrict__ scale, float* __restrict__ out, int nrows)
{
  extern __shared__ float sm[];
  float* sW1y = sm + OFF_W1Y;
  float* sW2  = sm + OFF_W2;
  float* sW3  = sm + OFF_W3;
  float* sB2  = sm + OFF_B2;
  float* sB3  = sm + OFF_B3;
  float* sS1  = sm + OFF_S1;

  const int tid = threadIdx.x;

  // ---- cooperative weight staging ----
  for (int j = tid; j < HID; j += TPB) {
    sW1y[j*4 + 0] = W1[0*HID + j];
    sW1y[j*4 + 1] = W1[1*HID + j];
    sW1y[j*4 + 2] = W1[2*HID + j];
    sW1y[j*4 + 3] = W1[64*HID + j];   // time row
  }
  for (int idx = tid; idx < HID*HID; idx += TPB) sW2[idx] = W2[idx];
  for (int j = tid; j < HID; j += TPB) {
    sW3[j*4 + 0] = W3[j*3 + 0];
    sW3[j*4 + 1] = W3[j*3 + 1];
    sW3[j*4 + 2] = W3[j*3 + 2];
    sW3[j*4 + 3] = 0.0f;
    sB2[j] = b2[j];
  }
  if (tid < 4) sB3[tid] = (tid < 3) ? b3[tid] : 0.0f;
  __syncthreads();

  const int row = blockIdx.x * TPB + tid;
  if (row >= nrows) return;

  // ---- prologue: s1[j] = b1[j] + sensory . W1[3:64, j]  (constant over all 60 evals) ----
  {
    float4 acc[16];
    const float4* b1v = (const float4*)b1;
    #pragma unroll
    for (int g = 0; g < 16; g++) acc[g] = __ldg(b1v + g);
    const float* srow = sens + (size_t)row * SENS;
    for (int s2 = 0; s2 < SENS; s2++) {
      float sv = __ldg(srow + s2);
      const float4* wr = (const float4*)(W1 + (3 + s2) * HID);
      #pragma unroll
      for (int g = 0; g < 16; g++) {
        float4 w = __ldg(wr + g);
        acc[g].x = fmaf(sv, w.x, acc[g].x);
        acc[g].y = fmaf(sv, w.y, acc[g].y);
        acc[g].z = fmaf(sv, w.z, acc[g].z);
        acc[g].w = fmaf(sv, w.w, acc[g].w);
      }
    }
    #pragma unroll
    for (int g = 0; g < 16; g++) {
      sS1[(4*g + 0)*TPB + tid] = acc[g].x;
      sS1[(4*g + 1)*TPB + tid] = acc[g].y;
      sS1[(4*g + 2)*TPB + tid] = acc[g].z;
      sS1[(4*g + 3)*TPB + tid] = acc[g].w;
    }
  }

  // ---- integrate ----
  float y0 = __ldg(pad0 + (size_t)row*3 + 0);
  float y1 = __ldg(pad0 + (size_t)row*3 + 1);
  float y2 = __ldg(pad0 + (size_t)row*3 + 2);
  const float sc = __ldg(scale);
  const float h = 1.0f / (float)NSTEPS;

  float k[6][3];   // dynamic-indexed store -> local mem; cheap vs 5K FFMA/eval

  #pragma unroll 1
  for (int st = 0; st < NSTEPS; st++) {
    float t0 = (float)st * h;

    #pragma unroll 1
    for (int s = 0; s < 6; s++) {
      float ys0 = y0, ys1 = y1, ys2 = y2;
      #pragma unroll
      for (int m = 0; m < 5; m++) {
        if (m < s) {
          float a = h * c_A[s][m];
          ys0 = fmaf(a, k[m][0], ys0);
          ys1 = fmaf(a, k[m][1], ys1);
          ys2 = fmaf(a, k[m][2], ys2);
        }
      }
      float ts = fmaf(c_C[s], h, t0);

      // ---- f(ts, ys): fused layer1+layer2 over hidden i ----
      float a2f[HID];
      #pragma unroll
      for (int j = 0; j < HID; j++) a2f[j] = sB2[j];

      #pragma unroll 4
      for (int i = 0; i < HID; i++) {
        const float4 wy = ((const float4*)sW1y)[i];
        float pre = sS1[i*TPB + tid];
        pre = fmaf(ys0, wy.x, pre);
        pre = fmaf(ys1, wy.y, pre);
        pre = fmaf(ys2, wy.z, pre);
        pre = fmaf(ts,  wy.w, pre);
        float hv = ftanh(pre);
        const float4* w2r = (const float4*)(sW2 + i*HID);
        #pragma unroll
        for (int g = 0; g < 16; g++) {
          float4 w = w2r[g];
          a2f[4*g + 0] = fmaf(hv, w.x, a2f[4*g + 0]);
          a2f[4*g + 1] = fmaf(hv, w.y, a2f[4*g + 1]);
          a2f[4*g + 2] = fmaf(hv, w.z, a2f[4*g + 2]);
          a2f[4*g + 3] = fmaf(hv, w.w, a2f[4*g + 3]);
        }
      }

      // ---- layer2 tanh + layer3 ----
      float o0 = sB3[0], o1 = sB3[1], o2 = sB3[2];
      #pragma unroll
      for (int i = 0; i < HID; i++) {
        float hv = ftanh(a2f[i]);
        const float4 w3 = ((const float4*)sW3)[i];
        o0 = fmaf(hv, w3.x, o0);
        o1 = fmaf(hv, w3.y, o1);
        o2 = fmaf(hv, w3.z, o2);
      }
      k[s][0] = ftanh(o0) * sc;
      k[s][1] = ftanh(o1) * sc;
      k[s][2] = ftanh(o2) * sc;
    }

    #pragma unroll
    for (int m = 0; m < 6; m++) {
      float bm = h * c_B[m];
      y0 = fmaf(bm, k[m][0], y0);
      y1 = fmaf(bm, k[m][1], y1);
      y2 = fmaf(bm, k[m][2], y2);
    }
  }

  out[(size_t)row*3 + 0] = y0;
  out[(size_t)row*3 + 1] = y1;
  out[(size_t)row*3 + 2] = y2;
}

extern "C" void kernel_launch(void* const* d_in, const int* in_sizes, int n_in,
                              void* d_out, int out_size) {
  const float* pad0  = (const float*)d_in[0];
  const float* sens  = (const float*)d_in[1];
  const float* W1    = (const float*)d_in[2];
  const float* b1    = (const float*)d_in[3];
  const float* W2    = (const float*)d_in[4];
  const float* b2    = (const float*)d_in[5];
  const float* W3    = (const float*)d_in[6];
  const float* b3    = (const float*)d_in[7];
  const float* scale = (const float*)d_in[8];
  float* out = (float*)d_out;

  const int nrows = in_sizes[0] / 3;
  const int smem_bytes = SMEM_FLOATS * (int)sizeof(float);   // ~51.5 KB -> needs opt-in
  cudaFuncSetAttribute(ode_kernel, cudaFuncAttributeMaxDynamicSharedMemorySize, smem_bytes);

  const int grid = (nrows + TPB - 1) / TPB;
  ode_kernel<<<grid, TPB, smem_bytes>>>(pad0, sens, W1, b1, W2, b2, W3, b3, scale, out, nrows);
}